// round 11
// baseline (speedup 1.0000x reference)
#include <cuda_runtime.h>
#include <cstdint>

#define T_STEPS    2000
#define LIF_STRIDE 2048
#define N_IN       8192
#define N_OUT      4096

// lif_input stored NEURON-MAJOR: g_lif[n * 2048 + t]
__device__ float g_lif[(size_t)N_OUT * LIF_STRIDE];

// ---------------------------------------------------------------------------
// FFMA2: d = a*b + d per 32-bit half, IEEE fp32 RN — bit-identical to two
// independent scalar FFMA chains.
// ---------------------------------------------------------------------------
__device__ __forceinline__ void ffma2(unsigned long long& d,
                                      unsigned long long a,
                                      unsigned long long b) {
    asm("fma.rn.f32x2 %0, %1, %2, %0;" : "+l"(d) : "l"(a), "l"(b));
}

// ---------------------------------------------------------------------------
// GEMM: lif[n][m] = sum_k A[m,k] * W[n,k], pure fp32, ascending-k FMA chain
// per output element (bit-identical to the reference reduction order).
// Tile 64(M) x 128(N), BK=16, 256 threads, per-thread 4x8 via 16 FFMA2/k.
// 1024 CTAs (98.9% wave balance), 2 CTAs/SM, ~85 regs (no spill).
// smem: A pre-DUPLICATED ({a,a} u64), B pre-PAIRED ({b0,b1} u64).
// ---------------------------------------------------------------------------
#define BM 64
#define BN 128
#define BK 16
#define NCHUNKS (N_IN / BK)          // 512
#define KROW_BYTES 512               // 64 u64 per k row
#define OFF_B  (BK * KROW_BYTES)     // 8192
#define STAGE_BYTES (2 * BK * KROW_BYTES)   // 16384
#define SMEM_TOTAL  (2 * STAGE_BYTES)       // 32768

struct LdRegs { float4 a; float4 b0, b1; };

__device__ __forceinline__ void ldg_chunk(const float* __restrict__ A,
                                          const float* __restrict__ B,
                                          int bm, int bn, int k0, int tid,
                                          LdRegs& r) {
    // A: 64 rows x 16 k = 256 float4; row = tid>>2, ko = (tid&3)*4
    int ar = bm + (tid >> 2); if (ar > T_STEPS - 1) ar = T_STEPS - 1;
    int koA = (tid & 3) * 4;
    r.a = *reinterpret_cast<const float4*>(&A[(size_t)ar * N_IN + k0 + koA]);
    // B: 64 pairs x 16 k; pair p = tid&63 -> rows bn+2p, bn+2p+1; ko = (tid>>6)*4
    int p   = tid & 63;
    int koB = (tid >> 6) * 4;
    r.b0 = *reinterpret_cast<const float4*>(&B[(size_t)(bn + 2 * p)     * N_IN + k0 + koB]);
    r.b1 = *reinterpret_cast<const float4*>(&B[(size_t)(bn + 2 * p + 1) * N_IN + k0 + koB]);
}

__device__ __forceinline__ void sts_chunk(char* stage, int tid, const LdRegs& r) {
    int rowA = tid >> 2;
    int koA  = (tid & 3) * 4;
    int p    = tid & 63;
    int koB  = (tid >> 6) * 4;
    const float* av = (const float*)&r.a;
    const float* b0 = (const float*)&r.b0;
    const float* b1 = (const float*)&r.b1;
    #pragma unroll
    for (int e = 0; e < 4; e++) {
        *reinterpret_cast<float2*>(stage + (size_t)(koA + e) * KROW_BYTES + rowA * 8) =
            make_float2(av[e], av[e]);
        *reinterpret_cast<float2*>(stage + OFF_B + (size_t)(koB + e) * KROW_BYTES + p * 8) =
            make_float2(b0[e], b1[e]);
    }
}

__global__ __launch_bounds__(256, 2)
void gemm_ffma2(const float* __restrict__ A,   // [2000, 8192]
                const float* __restrict__ B)   // [4096, 8192]
{
    extern __shared__ char smem[];
    const int tid = threadIdx.x;
    const int tx  = tid & 15;        // n group (0..15)
    const int ty  = tid >> 4;        // m group (0..15)
    const int bm  = blockIdx.y * BM;
    const int bn  = blockIdx.x * BN;

    unsigned long long acc[4][4];    // [m][n-pair], halves = (n_even, n_odd)
    #pragma unroll
    for (int i = 0; i < 4; i++)
        #pragma unroll
        for (int j = 0; j < 4; j++) acc[i][j] = 0ull;

    LdRegs regs;
    ldg_chunk(A, B, bm, bn, 0, tid, regs);

    for (int c = 0; c < NCHUNKS; c++) {
        char* stage = smem + (c & 1) * STAGE_BYTES;
        sts_chunk(stage, tid, regs);
        __syncthreads();
        if (c + 1 < NCHUNKS) ldg_chunk(A, B, bm, bn, (c + 1) * BK, tid, regs);

        const char* sA = stage;
        const char* sB = stage + OFF_B;
        #pragma unroll
        for (int k = 0; k < BK; k++) {
            unsigned long long ra[4], bb[4];
            #pragma unroll
            for (int i = 0; i < 4; i++)
                ra[i] = *reinterpret_cast<const unsigned long long*>(
                    sA + (size_t)k * KROW_BYTES + (ty * 4 + i) * 8);
            #pragma unroll
            for (int j = 0; j < 4; j++)
                bb[j] = *reinterpret_cast<const unsigned long long*>(
                    sB + (size_t)k * KROW_BYTES + (tx + 16 * j) * 8);
            #pragma unroll
            for (int i = 0; i < 4; i++)
                #pragma unroll
                for (int j = 0; j < 4; j++)
                    ffma2(acc[i][j], ra[i], bb[j]);
        }
        __syncthreads();
    }

    // Epilogue: scatter transposed into neuron-major g_lif[n][m]
    #pragma unroll
    for (int i = 0; i < 4; i++) {
        int m = bm + ty * 4 + i;
        if (m < T_STEPS) {
            #pragma unroll
            for (int j = 0; j < 4; j++) {
                int n0 = bn + 2 * (tx + 16 * j);
                float lo = __uint_as_float((uint32_t)(acc[i][j] & 0xFFFFFFFFull));
                float hi = __uint_as_float((uint32_t)(acc[i][j] >> 32));
                g_lif[(size_t)n0 * LIF_STRIDE + m]       = lo;
                g_lif[(size_t)(n0 + 1) * LIF_STRIDE + m] = hi;
            }
        }
    }
}

// ---------------------------------------------------------------------------
// LIF scan: neuron-major streaming input, float4 loads, 8-block prefetch.
// Elementwise ops match the reference bit-for-bit.
// ---------------------------------------------------------------------------
__global__ __launch_bounds__(32)
void lif_scan(const float* __restrict__ vth_p,
              const float* __restrict__ vrest_p,
              const float* __restrict__ vreset_p,
              const float* __restrict__ tref_p,
              const float* __restrict__ tau_p,
              float* __restrict__ out)
{
    const int j = blockIdx.x * 32 + threadIdx.x;

    const float Vth    = vth_p[j];
    const float Vrest  = vrest_p[j];
    const float Vreset = vreset_p[j];
    const float Tref   = tref_p[j];
    const float ktau   = __fmul_rn(0.001f, tau_p[j]);
    const float DT     = 0.001f;

    float v = Vrest, refrac = 0.f;
    out[j] = 0.f;   // t = 0 row

    const float* __restrict__ row = g_lif + (size_t)j * LIF_STRIDE;
    const int NBLK = T_STEPS / 8;   // 250

    float4 pf[16];
    #pragma unroll
    for (int b = 0; b < 8; b++) {
        pf[2 * b]     = *reinterpret_cast<const float4*>(row + 8 * b);
        pf[2 * b + 1] = *reinterpret_cast<const float4*>(row + 8 * b + 4);
    }

    for (int b = 0; b < NBLK; b++) {
        int slot = (b & 7) * 2;
        float vals[8];
        vals[0] = pf[slot].x;   vals[1] = pf[slot].y;
        vals[2] = pf[slot].z;   vals[3] = pf[slot].w;
        vals[4] = pf[slot+1].x; vals[5] = pf[slot+1].y;
        vals[6] = pf[slot+1].z; vals[7] = pf[slot+1].w;
        if (b + 8 < NBLK) {
            pf[slot]     = *reinterpret_cast<const float4*>(row + 8 * (b + 8));
            pf[slot + 1] = *reinterpret_cast<const float4*>(row + 8 * (b + 8) + 4);
        }
        #pragma unroll
        for (int u = 0; u < 8; u++) {
            int t = 8 * b + u;
            if (t == 0) continue;
            float inp = vals[u];
            v = __fsub_rn(v, __fmul_rn(ktau, __fsub_rn(v, Vrest)));
            if (refrac == 0.f) v = __fadd_rn(v, inp);
            refrac = (refrac > 0.f) ? __fsub_rn(refrac, DT) : 0.f;
            float d = __fsub_rn(v, Vth);
            float spike = (d >= 0.f) ? 1.f : 0.f;
            if (d >= 0.f) { refrac = Tref; v = Vreset; }
            out[(size_t)t * N_OUT + j] = spike;
        }
    }
}

// ===========================================================================
extern "C" void kernel_launch(void* const* d_in, const int* in_sizes, int n_in,
                              void* d_out, int out_size)
{
    const float* x      = (const float*)d_in[0];
    const float* weight = (const float*)d_in[1];
    const float* vth    = (const float*)d_in[2];
    const float* vrest  = (const float*)d_in[3];
    const float* vreset = (const float*)d_in[4];
    const float* tref   = (const float*)d_in[5];
    const float* tau    = (const float*)d_in[6];
    float* out = (float*)d_out;

    cudaFuncSetAttribute(gemm_ffma2,
                         cudaFuncAttributeMaxDynamicSharedMemorySize, SMEM_TOTAL);

    dim3 ggrid(N_OUT / BN, (T_STEPS + BM - 1) / BM);   // 32 x 32 = 1024 CTAs
    gemm_ffma2<<<ggrid, 256, SMEM_TOTAL>>>(x, weight);

    lif_scan<<<N_OUT / 32, 32>>>(vth, vrest, vreset, tref, tau, out);
}

// round 13
// speedup vs baseline: 1.4459x; 1.4459x over previous
#include <cuda_runtime.h>
#include <cstdint>

#define T_STEPS    2000
#define LIF_STRIDE 2048
#define N_IN       8192
#define N_OUT      4096

// lif_input stored NEURON-MAJOR: g_lif[n * 2048 + t]
__device__ float g_lif[(size_t)N_OUT * LIF_STRIDE];

// ---------------------------------------------------------------------------
// FFMA2: d = a*b + d per 32-bit half, IEEE fp32 RN — bit-identical to two
// independent scalar FFMA chains.
// ---------------------------------------------------------------------------
__device__ __forceinline__ void ffma2(unsigned long long& d,
                                      unsigned long long a,
                                      unsigned long long b) {
    asm("fma.rn.f32x2 %0, %1, %2, %0;" : "+l"(d) : "l"(a), "l"(b));
}

// ---------------------------------------------------------------------------
// GEMM: lif[n][m] = sum_k A[m,k] * W[n,k], pure fp32, ascending-k FMA chain
// per output element (bit-identical to the reference reduction order).
// Tile 112(M) x 256(N), BK=16, 256 threads, per-thread 7x16 via 56 FFMA2/k.
// 288 CTAs -> wave 2 is 94.6% full (vs 73% at 256 CTAs). occ 1.
// smem: A pre-DUPLICATED ({a,a} u64), B pre-PAIRED ({b0,b1} u64).
// ---------------------------------------------------------------------------
#define BM 112
#define BN 256
#define BK 16
#define NCHUNKS (N_IN / BK)          // 512
#define KROWA 896                    // 112 u64 per k row (A)
#define KROWB 1024                   // 128 pair-u64 per k row (B)
#define OFF_B  (BK * KROWA)          // 14336
#define STAGE_BYTES (BK * (KROWA + KROWB))   // 30720
#define SMEM_TOTAL  (2 * STAGE_BYTES)        // 61440

struct LdRegs { float4 a[2]; float4 b[4]; };

__device__ __forceinline__ void ldg_chunk(const float* __restrict__ A,
                                          const float* __restrict__ B,
                                          int bm, int bn, int k0, int tid,
                                          LdRegs& r) {
    // A: 112 rows; threads 0..223: row = tid/2, ko = (tid&1)*8
    if (tid < 224) {
        int ar = bm + (tid >> 1); if (ar > T_STEPS - 1) ar = T_STEPS - 1;
        int ko = (tid & 1) * 8;
        const float* ap = &A[(size_t)ar * N_IN + k0 + ko];
        r.a[0] = *reinterpret_cast<const float4*>(ap);
        r.a[1] = *reinterpret_cast<const float4*>(ap + 4);
    }
    // B: 128 pairs; p = tid/2 -> rows bn+2p, bn+2p+1; ko = (tid&1)*8
    int p  = tid >> 1;
    int ko = (tid & 1) * 8;
    const float* bp0 = &B[(size_t)(bn + 2 * p) * N_IN + k0 + ko];
    const float* bp1 = &B[(size_t)(bn + 2 * p + 1) * N_IN + k0 + ko];
    r.b[0] = *reinterpret_cast<const float4*>(bp0);
    r.b[1] = *reinterpret_cast<const float4*>(bp0 + 4);
    r.b[2] = *reinterpret_cast<const float4*>(bp1);
    r.b[3] = *reinterpret_cast<const float4*>(bp1 + 4);
}

__device__ __forceinline__ void sts_chunk(char* stage, int tid, const LdRegs& r) {
    int ko = (tid & 1) * 8;
    if (tid < 224) {
        int row = tid >> 1;
        const float* av = (const float*)&r.a[0];
        #pragma unroll
        for (int e = 0; e < 8; e++) {
            float a = av[e];
            *reinterpret_cast<float2*>(stage + (size_t)(ko + e) * KROWA + row * 8) =
                make_float2(a, a);
        }
    }
    {
        int p = tid >> 1;
        const float* bv0 = (const float*)&r.b[0];
        const float* bv1 = (const float*)&r.b[2];
        #pragma unroll
        for (int e = 0; e < 8; e++) {
            *reinterpret_cast<float2*>(stage + OFF_B + (size_t)(ko + e) * KROWB + p * 8) =
                make_float2(bv0[e], bv1[e]);
        }
    }
}

__global__ __launch_bounds__(256, 1)
void gemm_ffma2(const float* __restrict__ A,   // [2000, 8192]
                const float* __restrict__ B)   // [4096, 8192]
{
    extern __shared__ char smem[];
    const int tid = threadIdx.x;
    const int tx  = tid & 15;        // n group (0..15)
    const int ty  = tid >> 4;        // m group (0..15), 7 rows each
    const int bm  = blockIdx.y * BM;
    const int bn  = blockIdx.x * BN;

    unsigned long long acc[7][8];    // [m][n-pair], halves = (n_even, n_odd)
    #pragma unroll
    for (int i = 0; i < 7; i++)
        #pragma unroll
        for (int j = 0; j < 8; j++) acc[i][j] = 0ull;

    LdRegs regs;
    ldg_chunk(A, B, bm, bn, 0, tid, regs);

    for (int c = 0; c < NCHUNKS; c++) {
        char* stage = smem + (c & 1) * STAGE_BYTES;
        sts_chunk(stage, tid, regs);
        __syncthreads();
        if (c + 1 < NCHUNKS) ldg_chunk(A, B, bm, bn, (c + 1) * BK, tid, regs);

        const char* sA = stage;
        const char* sB = stage + OFF_B;
        #pragma unroll
        for (int k = 0; k < BK; k++) {
            unsigned long long ra[7], bb[8];
            #pragma unroll
            for (int i = 0; i < 7; i++)
                ra[i] = *reinterpret_cast<const unsigned long long*>(
                    sA + (size_t)k * KROWA + (ty * 7 + i) * 8);
            #pragma unroll
            for (int j = 0; j < 8; j++)
                bb[j] = *reinterpret_cast<const unsigned long long*>(
                    sB + (size_t)k * KROWB + (tx + 16 * j) * 8);
            #pragma unroll
            for (int i = 0; i < 7; i++)
                #pragma unroll
                for (int j = 0; j < 8; j++)
                    ffma2(acc[i][j], ra[i], bb[j]);
        }
        // Double-buffer safety: the next iteration's sts targets the OTHER
        // stage; a thread reaches it only after this barrier, which follows
        // all threads' reads of that stage from the previous iteration.
    }

    // Epilogue: scatter transposed into neuron-major g_lif[n][m]
    #pragma unroll
    for (int i = 0; i < 7; i++) {
        int m = bm + ty * 7 + i;
        if (m < T_STEPS) {
            #pragma unroll
            for (int j = 0; j < 8; j++) {
                int n0 = bn + 2 * (tx + 16 * j);
                float lo = __uint_as_float((uint32_t)(acc[i][j] & 0xFFFFFFFFull));
                float hi = __uint_as_float((uint32_t)(acc[i][j] >> 32));
                g_lif[(size_t)n0 * LIF_STRIDE + m]       = lo;
                g_lif[(size_t)(n0 + 1) * LIF_STRIDE + m] = hi;
            }
        }
    }
}

// ---------------------------------------------------------------------------
// LIF scan: neuron-major streaming input, float4 loads, 8-block prefetch.
// All conditionals as integer-compare + select (pred-as-data, 4 cyc) instead
// of float-pred guards/branches. Bit-exact equivalences:
//   - refrac >= 0 always, zero is +0  -> (bits==0) <=> (refrac==0)
//   - d = v - Vth can never be -0.0 (x-x = +0 in RN) -> sign-int test == (d>=0)
// ---------------------------------------------------------------------------
__global__ __launch_bounds__(32)
void lif_scan(const float* __restrict__ vth_p,
              const float* __restrict__ vrest_p,
              const float* __restrict__ vreset_p,
              const float* __restrict__ tref_p,
              const float* __restrict__ tau_p,
              float* __restrict__ out)
{
    const int j = blockIdx.x * 32 + threadIdx.x;

    const float Vth    = vth_p[j];
    const float Vrest  = vrest_p[j];
    const float Vreset = vreset_p[j];
    const float Tref   = tref_p[j];
    const float ktau   = __fmul_rn(0.001f, tau_p[j]);
    const float DT     = 0.001f;

    float v = Vrest, refrac = 0.f;
    out[j] = 0.f;   // t = 0 row

    const float* __restrict__ row = g_lif + (size_t)j * LIF_STRIDE;
    const int NBLK = T_STEPS / 8;   // 250

    float4 pf[16];
    #pragma unroll
    for (int b = 0; b < 8; b++) {
        pf[2 * b]     = *reinterpret_cast<const float4*>(row + 8 * b);
        pf[2 * b + 1] = *reinterpret_cast<const float4*>(row + 8 * b + 4);
    }

    for (int b = 0; b < NBLK; b++) {
        int slot = (b & 7) * 2;
        float vals[8];
        vals[0] = pf[slot].x;   vals[1] = pf[slot].y;
        vals[2] = pf[slot].z;   vals[3] = pf[slot].w;
        vals[4] = pf[slot+1].x; vals[5] = pf[slot+1].y;
        vals[6] = pf[slot+1].z; vals[7] = pf[slot+1].w;
        if (b + 8 < NBLK) {
            pf[slot]     = *reinterpret_cast<const float4*>(row + 8 * (b + 8));
            pf[slot + 1] = *reinterpret_cast<const float4*>(row + 8 * (b + 8) + 4);
        }
        #pragma unroll
        for (int u = 0; u < 8; u++) {
            int t = 8 * b + u;
            if (t == 0) continue;
            float inp = vals[u];
            // leak
            v = __fsub_rn(v, __fmul_rn(ktau, __fsub_rn(v, Vrest)));
            // gate on refractory state (captured BEFORE countdown)
            unsigned rb = __float_as_uint(refrac);
            float vadd  = __fadd_rn(v, inp);
            v = (rb == 0u) ? vadd : v;
            // refractory countdown
            float rdec = __fsub_rn(refrac, DT);
            refrac = (rb == 0u) ? 0.f : rdec;
            // spike + reset (sign-int test, no -0 case possible)
            float d  = __fsub_rn(v, Vth);
            int   ds = __float_as_int(d);
            float spike = (ds >= 0) ? 1.f : 0.f;
            v      = (ds >= 0) ? Vreset : v;
            refrac = (ds >= 0) ? Tref : refrac;
            out[(size_t)t * N_OUT + j] = spike;
        }
    }
}

// ===========================================================================
extern "C" void kernel_launch(void* const* d_in, const int* in_sizes, int n_in,
                              void* d_out, int out_size)
{
    const float* x      = (const float*)d_in[0];
    const float* weight = (const float*)d_in[1];
    const float* vth    = (const float*)d_in[2];
    const float* vrest  = (const float*)d_in[3];
    const float* vreset = (const float*)d_in[4];
    const float* tref   = (const float*)d_in[5];
    const float* tau    = (const float*)d_in[6];
    float* out = (float*)d_out;

    cudaFuncSetAttribute(gemm_ffma2,
                         cudaFuncAttributeMaxDynamicSharedMemorySize, SMEM_TOTAL);

    dim3 ggrid(N_OUT / BN, (T_STEPS + BM - 1) / BM);   // 16 x 18 = 288 CTAs
    gemm_ffma2<<<ggrid, 256, SMEM_TOTAL>>>(x, weight);

    lif_scan<<<N_OUT / 32, 32>>>(vth, vrest, vreset, tref, tau, out);
}